// round 2
// baseline (speedup 1.0000x reference)
#include <cuda_runtime.h>

#define N_NODES 160000
#define NODES_PER_GRAPH 20000
#define N_GRAPHS 8
#define N_EDGES 5120000
#define HID 16
#define O1 4000
#define O2 800
#define O3 160
#define NOUT 10

// -------- scratch (device globals: no allocation allowed) --------
__device__ __align__(16) float d_agg1[N_NODES];
__device__ __align__(16) float d_agg2[N_NODES];
__device__ __align__(16) float d_p[N_NODES];
__device__ __align__(16) float d_q[N_NODES];
__device__ __align__(16) float d_gT[NODES_PER_GRAPH * 8];   // [node_in_graph][batch]
__device__ __align__(16) float d_h1T[O1 * 8];               // [o][batch]
__device__ __align__(16) float d_h2T[O2 * 8];
__device__ __align__(16) float d_h3T[O3 * 8];

// -------- zero accumulators (out buffers are overwritten elsewhere) ------
__global__ void k_zero() {
    int i = blockIdx.x * blockDim.x + threadIdx.x;
    if (i < N_NODES) { d_agg1[i] = 0.f; d_agg2[i] = 0.f; }
}

// -------- scalar edge scatter: agg[tgt] += ew * val[src] -----------------
// pass 0: val = x (param), agg = d_agg1 ; pass 1: val = d_p, agg = d_agg2
__global__ void k_scatter(const int* __restrict__ src, const int* __restrict__ tgt,
                          const float* __restrict__ ew, const float* __restrict__ val_in,
                          int pass) {
    const float* __restrict__ val = (pass == 0) ? val_in : d_p;
    float* __restrict__ agg = (pass == 0) ? d_agg1 : d_agg2;
    int t = blockIdx.x * blockDim.x + threadIdx.x;
    int e0 = t * 4;
    if (e0 + 3 < N_EDGES) {
        int4   s = *reinterpret_cast<const int4*>(src + e0);
        int4   g = *reinterpret_cast<const int4*>(tgt + e0);
        float4 w = *reinterpret_cast<const float4*>(ew + e0);
        atomicAdd(&agg[g.x], w.x * __ldg(&val[s.x]));
        atomicAdd(&agg[g.y], w.y * __ldg(&val[s.y]));
        atomicAdd(&agg[g.z], w.z * __ldg(&val[s.z]));
        atomicAdd(&agg[g.w], w.w * __ldg(&val[s.w]));
    } else if (e0 < N_EDGES) {
        for (int e = e0; e < N_EDGES; e++)
            atomicAdd(&agg[tgt[e]], ew[e] * __ldg(&val[src[e]]));
    }
}

// -------- per-node: h = relu(conv1), fold conv2's matmuls to scalars -----
// h[f] = relu(agg1*Wr1[f] + x*Ws1[f] + br1[f]); p = h.Wr2 ; q = h.Ws2
__global__ void k_node1(const float* __restrict__ x,
                        const float* __restrict__ Wr1, const float* __restrict__ br1,
                        const float* __restrict__ Ws1, const float* __restrict__ Wr2,
                        const float* __restrict__ Ws2) {
    __shared__ float swr1[HID], sbr1[HID], sws1[HID], swr2[HID], sws2[HID];
    if (threadIdx.x < HID) {
        swr1[threadIdx.x] = Wr1[threadIdx.x];
        sbr1[threadIdx.x] = br1[threadIdx.x];
        sws1[threadIdx.x] = Ws1[threadIdx.x];
        swr2[threadIdx.x] = Wr2[threadIdx.x];
        sws2[threadIdx.x] = Ws2[threadIdx.x];
    }
    __syncthreads();
    int n = blockIdx.x * blockDim.x + threadIdx.x;
    if (n >= N_NODES) return;
    float a = d_agg1[n];
    float xv = x[n];
    float p = 0.f, q = 0.f;
#pragma unroll
    for (int f = 0; f < HID; f++) {
        float h = fmaf(a, swr1[f], fmaf(xv, sws1[f], sbr1[f]));
        h = fmaxf(h, 0.f);
        p = fmaf(swr2[f], h, p);
        q = fmaf(sws2[f], h, q);
    }
    d_p[n] = p;
    d_q[n] = q;
}

// -------- per-node: h2 = agg2 + br2 + q, scatter into gT [i][batch] ------
__global__ void k_node2(const float* __restrict__ br2) {
    int n = blockIdx.x * blockDim.x + threadIdx.x;
    if (n >= N_NODES) return;
    float h2 = d_agg2[n] + __ldg(br2) + d_q[n];
    int b = n / NODES_PER_GRAPH;
    int i = n - b * NODES_PER_GRAPH;
    d_gT[i * 8 + b] = h2;
}

// -------- dense layer: outT[o][b] = act( sum_k W[o][k]*inT[k][b] + bias[o] )
// One block owns 8 output rows x 8 batches; 256 threads stride k.
// Activation traffic == weight traffic (both 1 load per 8 FMA per operand).
template <bool RELU>
__global__ void k_gemm8(const float* __restrict__ W, const float* __restrict__ bias,
                        const float* __restrict__ inT, float* __restrict__ outT, int K) {
    const int tid = threadIdx.x;
    const int o0 = blockIdx.x * 8;
    float acc[8][8];
#pragma unroll
    for (int r = 0; r < 8; r++)
#pragma unroll
        for (int b = 0; b < 8; b++) acc[r][b] = 0.f;

    const float* Wb = W + (size_t)o0 * K;
    for (int k = tid; k < K; k += 256) {
        float4 g0 = *reinterpret_cast<const float4*>(inT + k * 8);
        float4 g1 = *reinterpret_cast<const float4*>(inT + k * 8 + 4);
        float gv[8] = {g0.x, g0.y, g0.z, g0.w, g1.x, g1.y, g1.z, g1.w};
#pragma unroll
        for (int r = 0; r < 8; r++) {
            float w = __ldg(Wb + (size_t)r * K + k);
#pragma unroll
            for (int b = 0; b < 8; b++) acc[r][b] = fmaf(w, gv[b], acc[r][b]);
        }
    }

    // staged shared-memory reduction of 64 accumulators over 256 threads
    __shared__ float s[32 * 256];  // 32 KB
#pragma unroll
    for (int half = 0; half < 2; half++) {
        __syncthreads();
#pragma unroll
        for (int j = 0; j < 32; j++) {
            int idx = half * 32 + j;
            s[j * 256 + tid] = acc[idx >> 3][idx & 7];
        }
        __syncthreads();
        int j = tid >> 3;      // 0..31 : which value
        int part = tid & 7;    // 0..7  : which slice of 256 partials
        float v = 0.f;
#pragma unroll
        for (int t = 0; t < 32; t++) v += s[j * 256 + part + t * 8];
        v += __shfl_down_sync(0xffffffffu, v, 4, 8);
        v += __shfl_down_sync(0xffffffffu, v, 2, 8);
        v += __shfl_down_sync(0xffffffffu, v, 1, 8);
        if (part == 0) {
            int idx = half * 32 + j;
            int r = idx >> 3, b = idx & 7;
            float o = v + __ldg(&bias[o0 + r]);
            if (RELU) o = fmaxf(o, 0.f);
            outT[(o0 + r) * 8 + b] = o;
        }
    }
}

// -------- final 10x160 layer + log_softmax ------------------------------
__global__ void k_final(const float* __restrict__ W4, const float* __restrict__ b4,
                        float* __restrict__ out) {
    __shared__ float logits[N_GRAPHS][NOUT];
    int tid = threadIdx.x;
    if (tid < N_GRAPHS * NOUT) {
        int o = tid / N_GRAPHS;
        int b = tid % N_GRAPHS;
        float v = __ldg(&b4[o]);
        for (int k = 0; k < O3; k++)
            v = fmaf(__ldg(&W4[o * O3 + k]), d_h3T[k * 8 + b], v);
        logits[b][o] = v;
    }
    __syncthreads();
    if (tid < N_GRAPHS) {
        float m = -1e30f;
#pragma unroll
        for (int o = 0; o < NOUT; o++) m = fmaxf(m, logits[tid][o]);
        float sum = 0.f;
#pragma unroll
        for (int o = 0; o < NOUT; o++) sum += expf(logits[tid][o] - m);
        float lse = m + logf(sum);
#pragma unroll
        for (int o = 0; o < NOUT; o++) out[tid * NOUT + o] = logits[tid][o] - lse;
    }
}

extern "C" void kernel_launch(void* const* d_in, const int* in_sizes, int n_in,
                              void* d_out, int out_size) {
    const float* x   = (const float*)d_in[0];
    const float* ew  = (const float*)d_in[1];
    const float* Wr1 = (const float*)d_in[2];
    const float* br1 = (const float*)d_in[3];
    const float* Ws1 = (const float*)d_in[4];
    const float* Wr2 = (const float*)d_in[5];
    const float* br2 = (const float*)d_in[6];
    const float* Ws2 = (const float*)d_in[7];
    const float* W1  = (const float*)d_in[8];
    const float* b1  = (const float*)d_in[9];
    const float* W2  = (const float*)d_in[10];
    const float* b2  = (const float*)d_in[11];
    const float* W3  = (const float*)d_in[12];
    const float* b3  = (const float*)d_in[13];
    const float* W4  = (const float*)d_in[14];
    const float* b4  = (const float*)d_in[15];
    const int*   ei  = (const int*)d_in[16];
    float* out = (float*)d_out;

    const int* src = ei;
    const int* tgt = ei + N_EDGES;

    const int NODE_BLOCKS = (N_NODES + 255) / 256;             // 625
    const int EDGE_BLOCKS = (N_EDGES / 4 + 255) / 256;         // 5000

    // device globals for scratch; pointers resolved inside kernels
    float* gT  = nullptr;  // sentinel: kernels use device symbols directly

    k_zero<<<NODE_BLOCKS, 256>>>();
    k_scatter<<<EDGE_BLOCKS, 256>>>(src, tgt, ew, x, 0);
    k_node1<<<NODE_BLOCKS, 256>>>(x, Wr1, br1, Ws1, Wr2, Ws2);
    k_scatter<<<EDGE_BLOCKS, 256>>>(src, tgt, ew, nullptr, 1);
    k_node2<<<NODE_BLOCKS, 256>>>(br2);

    // d_gT / d_h*T are device symbols; get device pointers via kernel args is
    // not needed — template kernels take raw pointers, so pass symbol addrs
    // through a tiny launch trampoline: use cudaGetSymbolAddress-free path by
    // launching dedicated wrappers below.
    (void)gT;

    // GEMM chain via symbol-addressed wrappers
    extern void launch_gemms(const float*, const float*, const float*, const float*,
                             const float*, const float*, const float*, const float*, float*);
    launch_gemms(W1, b1, W2, b2, W3, b3, W4, b4, out);
}

// Wrappers: take device-symbol addresses inside __global__-adjacent TU scope.
// (Device symbols are valid device pointers when referenced from device code;
// from host we obtain them via small forwarding kernels is unnecessary —
// &d_gT[0] in host code is NOT valid, so we use dedicated kernels instead.)
__global__ void k_gemm8_1(const float* __restrict__ W, const float* __restrict__ bias) {
    // never called; placeholder removed
}

void launch_gemms(const float* W1, const float* b1, const float* W2, const float* b2,
                  const float* W3, const float* b3, const float* W4, const float* b4,
                  float* out) {
    // Resolve device symbol addresses once per call (host API, graph-safe:
    // cudaGetSymbolAddress is not a stream operation).
    static float *p_gT = nullptr, *p_h1 = nullptr, *p_h2 = nullptr, *p_h3 = nullptr;
    if (!p_gT) {
        cudaGetSymbolAddress((void**)&p_gT, d_gT);
        cudaGetSymbolAddress((void**)&p_h1, d_h1T);
        cudaGetSymbolAddress((void**)&p_h2, d_h2T);
        cudaGetSymbolAddress((void**)&p_h3, d_h3T);
    }
    k_gemm8<true ><<<O1 / 8, 256>>>(W1, b1, p_gT, p_h1, NODES_PER_GRAPH);
    k_gemm8<true ><<<O2 / 8, 256>>>(W2, b2, p_h1, p_h2, O1);
    k_gemm8<true ><<<O3 / 8, 256>>>(W3, b3, p_h2, p_h3, O2);
    k_final<<<1, 128>>>(W4, b4, out);
}